// round 12
// baseline (speedup 1.0000x reference)
#include <cuda_runtime.h>

#define B_TOTAL 8192
#define H_      200
#define G4      800     // 4*H
#define T_      100
#define OUTC    400     // SEQ_LEN*NUM_AXIS
#define TILE_B  64
#define NCTA    (B_TOTAL / TILE_B)   // 128
#define NTHREADS 800                 // 16 b-groups * 50 j-groups (25 warps)
#define BGROUPS  16

// Cell-state scratch (allocation-free rule: __device__ global array). 19.66 MB, L2-resident.
__device__ float g_c[(size_t)3 * B_TOTAL * H_];

typedef unsigned long long u64;

__device__ __forceinline__ u64 pack2(float x, float y) {
    u64 r; asm("mov.b64 %0, {%1, %2};" : "=l"(r) : "f"(x), "f"(y)); return r;
}
__device__ __forceinline__ float2 unpack2(u64 v) {
    float2 f; asm("mov.b64 {%0, %1}, %2;" : "=f"(f.x), "=f"(f.y) : "l"(v)); return f;
}
// Packed f32x2 FMA (Blackwell): 2 fp32 MACs per instruction slot.
__device__ __forceinline__ void fma2(u64& acc, u64 a, u64 b) {
    asm("fma.rn.f32x2 %0, %1, %2, %0;" : "+l"(acc) : "l"(a), "l"(b));
}

__device__ __forceinline__ float sigm_(float x) { return 1.0f / (1.0f + __expf(-x)); }
__device__ __forceinline__ float tanh_(float x) {
    float e = __expf(-2.0f * fabsf(x));
    float r = (1.0f - e) / (1.0f + e);
    return copysignf(r, x);
}

// acc[b][jpair] += hsm[k][b0+b] * Wp[k*LD + (0..3)]  for k in [0,200)
template<int LD>
__device__ __forceinline__ void mm_accum(u64 acc[4][2],
        const float* __restrict__ Wp, const float* hsm, int b0)
{
#pragma unroll 4
    for (int k = 0; k < H_; ++k) {
        float4 wv = *reinterpret_cast<const float4*>(Wp + k * LD);
        float4 hv = *reinterpret_cast<const float4*>(hsm + k * TILE_B + b0);
        u64 w01 = pack2(wv.x, wv.y);
        u64 w23 = pack2(wv.z, wv.w);
        u64 hh;
        hh = pack2(hv.x, hv.x); fma2(acc[0][0], w01, hh); fma2(acc[0][1], w23, hh);
        hh = pack2(hv.y, hv.y); fma2(acc[1][0], w01, hh); fma2(acc[1][1], w23, hh);
        hh = pack2(hv.z, hv.z); fma2(acc[2][0], w01, hh); fma2(acc[2][1], w23, hh);
        hh = pack2(hv.w, hv.w); fma2(acc[3][0], w01, hh); fma2(acc[3][1], w23, hh);
    }
}

// Fused dual-matrix accumulate: acc += hin@W + hrec@U (both [H_ x G4], column slice j0).
__device__ __forceinline__ void mm_accum2(u64 acc[4][2],
        const float* __restrict__ Wp, const float* __restrict__ Up,
        const float* hin, const float* hrec, int b0)
{
#pragma unroll 4
    for (int k = 0; k < H_; ++k) {
        float4 wv = *reinterpret_cast<const float4*>(Wp + k * G4);
        float4 uv = *reinterpret_cast<const float4*>(Up + k * G4);
        float4 hv = *reinterpret_cast<const float4*>(hin + k * TILE_B + b0);
        float4 gv = *reinterpret_cast<const float4*>(hrec + k * TILE_B + b0);
        u64 w01 = pack2(wv.x, wv.y);
        u64 w23 = pack2(wv.z, wv.w);
        u64 u01 = pack2(uv.x, uv.y);
        u64 u23 = pack2(uv.z, uv.w);
        u64 hh;
        hh = pack2(hv.x, hv.x); fma2(acc[0][0], w01, hh); fma2(acc[0][1], w23, hh);
        hh = pack2(hv.y, hv.y); fma2(acc[1][0], w01, hh); fma2(acc[1][1], w23, hh);
        hh = pack2(hv.z, hv.z); fma2(acc[2][0], w01, hh); fma2(acc[2][1], w23, hh);
        hh = pack2(hv.w, hv.w); fma2(acc[3][0], w01, hh); fma2(acc[3][1], w23, hh);
        hh = pack2(gv.x, gv.x); fma2(acc[0][0], u01, hh); fma2(acc[0][1], u23, hh);
        hh = pack2(gv.y, gv.y); fma2(acc[1][0], u01, hh); fma2(acc[1][1], u23, hh);
        hh = pack2(gv.z, gv.z); fma2(acc[2][0], u01, hh); fma2(acc[2][1], u23, hh);
        hh = pack2(gv.w, gv.w); fma2(acc[3][0], u01, hh); fma2(acc[3][1], u23, hh);
    }
}

// One gate's pre-activation z[b][j] for the thread's 4b x 4j tile.
// gate: 0=i, 1=f, 2=g, 3=o.  z = bias + (layer0 ? x*W0row : hin@W) + hrec@U
__device__ __forceinline__ void gate4(
    float g[4][4], int gate,
    const float* __restrict__ W, const float* __restrict__ U,
    const float* __restrict__ bias,
    const float* hin, const float* hrec, const float* xbuf,
    int b0, int j0, bool layer0)
{
    u64 acc[4][2];
    float4 bv = *reinterpret_cast<const float4*>(bias + gate * H_ + j0);
    u64 b01 = pack2(bv.x, bv.y), b23 = pack2(bv.z, bv.w);
#pragma unroll
    for (int b = 0; b < 4; ++b) { acc[b][0] = b01; acc[b][1] = b23; }

    if (layer0) {
        // input dim 1: z += x[b] * W0[0][col]
        float4 wv = *reinterpret_cast<const float4*>(W + gate * H_ + j0);
        u64 w01 = pack2(wv.x, wv.y), w23 = pack2(wv.z, wv.w);
        float4 xv = *reinterpret_cast<const float4*>(xbuf + b0);
        u64 hh;
        hh = pack2(xv.x, xv.x); fma2(acc[0][0], w01, hh); fma2(acc[0][1], w23, hh);
        hh = pack2(xv.y, xv.y); fma2(acc[1][0], w01, hh); fma2(acc[1][1], w23, hh);
        hh = pack2(xv.z, xv.z); fma2(acc[2][0], w01, hh); fma2(acc[2][1], w23, hh);
        hh = pack2(xv.w, xv.w); fma2(acc[3][0], w01, hh); fma2(acc[3][1], w23, hh);
        mm_accum<G4>(acc, U + gate * H_ + j0, hrec, b0);
    } else {
        mm_accum2(acc, W + gate * H_ + j0, U + gate * H_ + j0, hin, hrec, b0);
    }

#pragma unroll
    for (int b = 0; b < 4; ++b) {
        float2 p0 = unpack2(acc[b][0]), p1 = unpack2(acc[b][1]);
        g[b][0] = p0.x; g[b][1] = p0.y; g[b][2] = p1.x; g[b][3] = p1.y;
    }
}

__device__ __forceinline__ void lstm_layer(
    int t,
    const float* __restrict__ W, const float* __restrict__ U,
    const float* __restrict__ bias,
    const float* hin, float* hrec, const float* xbuf,
    float* __restrict__ cptr,   // c state for this CTA's batch tile: [TILE_B][H_]
    int b0, int j0, bool layer0)
{
    // Phase f: cnew = sigmoid(f) * c_old
    float fg[4][4];
    gate4(fg, 1, W, U, bias, hin, hrec, xbuf, b0, j0, layer0);
    float cnew[4][4];
#pragma unroll
    for (int b = 0; b < 4; ++b) {
        float4 c4 = make_float4(0.f, 0.f, 0.f, 0.f);
        if (t > 0) c4 = *reinterpret_cast<const float4*>(cptr + (b0 + b) * H_ + j0);
        cnew[b][0] = sigm_(fg[b][0]) * c4.x;
        cnew[b][1] = sigm_(fg[b][1]) * c4.y;
        cnew[b][2] = sigm_(fg[b][2]) * c4.z;
        cnew[b][3] = sigm_(fg[b][3]) * c4.w;
    }
    // Phase i
    float iv[4][4];
    gate4(iv, 0, W, U, bias, hin, hrec, xbuf, b0, j0, layer0);
#pragma unroll
    for (int b = 0; b < 4; ++b)
#pragma unroll
        for (int j = 0; j < 4; ++j) iv[b][j] = sigm_(iv[b][j]);
    // Phase g: cnew += sigmoid(i)*tanh(g); store c
    {
        float gg[4][4];
        gate4(gg, 2, W, U, bias, hin, hrec, xbuf, b0, j0, layer0);
#pragma unroll
        for (int b = 0; b < 4; ++b) {
#pragma unroll
            for (int j = 0; j < 4; ++j) cnew[b][j] += iv[b][j] * tanh_(gg[b][j]);
            *reinterpret_cast<float4*>(cptr + (b0 + b) * H_ + j0) =
                make_float4(cnew[b][0], cnew[b][1], cnew[b][2], cnew[b][3]);
        }
    }
    // Phase o: h = sigmoid(o) * tanh(cnew)
    float og[4][4];
    gate4(og, 3, W, U, bias, hin, hrec, xbuf, b0, j0, layer0);
    float hnew[4][4];
#pragma unroll
    for (int b = 0; b < 4; ++b)
#pragma unroll
        for (int j = 0; j < 4; ++j) hnew[b][j] = sigm_(og[b][j]) * tanh_(cnew[b][j]);

    __syncthreads();   // all reads of old hrec done
#pragma unroll
    for (int j = 0; j < 4; ++j) {
        *reinterpret_cast<float4*>(hrec + (j0 + j) * TILE_B + b0) =
            make_float4(hnew[0][j], hnew[1][j], hnew[2][j], hnew[3][j]);
    }
    __syncthreads();   // new hrec visible
}

__global__ void __launch_bounds__(NTHREADS, 1) lstm3_kernel(
    const float* __restrict__ x,
    const float* __restrict__ W0, const float* __restrict__ U0, const float* __restrict__ b0v,
    const float* __restrict__ W1, const float* __restrict__ U1, const float* __restrict__ b1v,
    const float* __restrict__ W2, const float* __restrict__ U2, const float* __restrict__ b2v,
    const float* __restrict__ Wfc, const float* __restrict__ bfc,
    float* __restrict__ out)
{
    extern __shared__ float sm[];
    float* hs0  = sm;                       // [H_][TILE_B] k-major
    float* hs1  = sm + H_ * TILE_B;
    float* hs2  = sm + 2 * H_ * TILE_B;
    float* xbuf = sm + 3 * H_ * TILE_B;     // [TILE_B]

    const int tid   = threadIdx.x;
    const int bbase = blockIdx.x * TILE_B;
    // Transposed mapping: b-groups fastest within a warp.
    // A warp covers 16 b-groups x 2 j-groups => weight LDG.128 hits only 2
    // distinct 16B chunks (one 128B line, 1 wavefront, broadcast) instead of
    // 32 distinct chunks (4 wavefronts). LDS h becomes 2 wavefronts.
    const int bg = tid & (BGROUPS - 1);
    const int jg = tid >> 4;
    const int b0 = bg * 4, j0 = jg * 4;

    for (int i = tid; i < 3 * H_ * TILE_B; i += NTHREADS) sm[i] = 0.0f;
    __syncthreads();

    float* c0 = g_c + ((size_t)0 * B_TOTAL + bbase) * H_;
    float* c1 = g_c + ((size_t)1 * B_TOTAL + bbase) * H_;
    float* c2 = g_c + ((size_t)2 * B_TOTAL + bbase) * H_;

    for (int t = 0; t < T_; ++t) {
        if (tid < TILE_B) xbuf[tid] = x[(size_t)(bbase + tid) * T_ + t];
        __syncthreads();
        lstm_layer(t, W0, U0, b0v, nullptr, hs0, xbuf, c0, b0, j0, true);
        lstm_layer(t, W1, U1, b1v, hs0,    hs1, xbuf, c1, b0, j0, false);
        lstm_layer(t, W2, U2, b2v, hs1,    hs2, xbuf, c2, b0, j0, false);
    }

    // Dense head: y[b][m] = tanh(h2[b] @ Wfc[:,m] + bfc[m]),  m in [0,400)
#pragma unroll
    for (int pass = 0; pass < 2; ++pass) {
        const int m0 = pass * H_ + j0;   // covers [0,200) then [200,400)
        u64 acc[4][2];
        float4 bv = *reinterpret_cast<const float4*>(bfc + m0);
        u64 p01 = pack2(bv.x, bv.y), p23 = pack2(bv.z, bv.w);
#pragma unroll
        for (int b = 0; b < 4; ++b) { acc[b][0] = p01; acc[b][1] = p23; }
        mm_accum<OUTC>(acc, Wfc + m0, hs2, b0);
#pragma unroll
        for (int b = 0; b < 4; ++b) {
            float2 q0 = unpack2(acc[b][0]), q1 = unpack2(acc[b][1]);
            float4 y = make_float4(tanh_(q0.x), tanh_(q0.y), tanh_(q1.x), tanh_(q1.y));
            *reinterpret_cast<float4*>(out + (size_t)(bbase + b0 + b) * OUTC + m0) = y;
        }
    }
}

extern "C" void kernel_launch(void* const* d_in, const int* in_sizes, int n_in,
                              void* d_out, int out_size) {
    (void)in_sizes; (void)n_in; (void)out_size;
    const float* x   = (const float*)d_in[0];
    const float* W0  = (const float*)d_in[1];
    const float* U0  = (const float*)d_in[2];
    const float* b0v = (const float*)d_in[3];
    const float* W1  = (const float*)d_in[4];
    const float* U1  = (const float*)d_in[5];
    const float* b1v = (const float*)d_in[6];
    const float* W2  = (const float*)d_in[7];
    const float* U2  = (const float*)d_in[8];
    const float* b2v = (const float*)d_in[9];
    const float* Wfc = (const float*)d_in[10];
    const float* bfc = (const float*)d_in[11];
    float* out = (float*)d_out;

    const int smem_bytes = (3 * H_ * TILE_B + TILE_B) * (int)sizeof(float);  // 153,856 B
    cudaFuncSetAttribute(lstm3_kernel, cudaFuncAttributeMaxDynamicSharedMemorySize, smem_bytes);
    lstm3_kernel<<<NCTA, NTHREADS, smem_bytes>>>(
        x, W0, U0, b0v, W1, U1, b1v, W2, U2, b2v, Wfc, bfc, out);
}

// round 14
// speedup vs baseline: 2.9516x; 2.9516x over previous
#include <cuda_runtime.h>
#include <cstdint>

#define B_TOTAL 8192
#define H_      200
#define T_      100
#define OUTC    400
#define TILE_B  64
#define NCTA    128
#define NTHREADS 256      // 8 warps: wb in {0,1} (32 batch rows each), wc in {0..3} (n-tile slices)

// ---- __device__ scratch (allocation-free rule) ----
// B fragments, tf32-rounded: L0 (U0 only): 4*25*25 tiles; L1,L2: 4*50*25 tiles. 64 floats/tile.
__device__ float g_bf[12500 * 64];                                   // 3.2 MB
// c-state in C-fragment order: [cta][layer][warp][mi2][ni7][lane32][4]
__device__ float g_cbuf[(size_t)NCTA * 3 * 8 * 2 * 7 * 32 * 4];      // 22 MB, L2-resident

typedef unsigned int u32;

__device__ __forceinline__ float tf32f(float v) {
    u32 r; asm("cvt.rna.tf32.f32 %0, %1;" : "=r"(r) : "f"(v));
    return __uint_as_float(r);
}
__device__ __forceinline__ void mma_tf32(float c[4], const uint4& a, float2 b) {
    asm volatile(
        "mma.sync.aligned.m16n8k8.row.col.f32.tf32.tf32.f32 "
        "{%0,%1,%2,%3}, {%4,%5,%6,%7}, {%8,%9}, {%0,%1,%2,%3};"
        : "+f"(c[0]), "+f"(c[1]), "+f"(c[2]), "+f"(c[3])
        : "r"(a.x), "r"(a.y), "r"(a.z), "r"(a.w),
          "r"(__float_as_uint(b.x)), "r"(__float_as_uint(b.y)));
}
__device__ __forceinline__ float sigm_(float x) { return 1.0f / (1.0f + __expf(-x)); }
__device__ __forceinline__ float tanh_(float x) {
    float e = __expf(-2.0f * fabsf(x));
    float r = (1.0f - e) / (1.0f + e);
    return copysignf(r, x);
}

// ---------------- weight reshuffle: row-major [K][800] -> B-fragment order ----------------
// Fragment map (m16n8k8 tf32, B col-major 8x8): b0 at (k=lane&3, n=lane>>2), b1 at (k+4, n).
// Tile order: L0: gate*625 + kt*25 + nt ; L1: 2500 + gate*1250 + kt*25 + nt ; L2: 7500 + ...
__global__ void prep_kernel(const float* __restrict__ U0,
                            const float* __restrict__ W1, const float* __restrict__ U1,
                            const float* __restrict__ W2, const float* __restrict__ U2) {
    int g = blockIdx.x * blockDim.x + threadIdx.x;
    if (g >= 12500 * 32) return;
    int tile = g >> 5, lane = g & 31;
    int gate, kt, nt;
    const float* src;
    int kb;
    if (tile < 2500) {
        int t = tile; gate = t / 625; t %= 625; kt = t / 25; nt = t % 25;
        src = U0; kb = kt * 8;
    } else if (tile < 7500) {
        int t = tile - 2500; gate = t / 1250; t %= 1250; kt = t / 25; nt = t % 25;
        if (kt < 25) { src = W1; kb = kt * 8; } else { src = U1; kb = (kt - 25) * 8; }
    } else {
        int t = tile - 7500; gate = t / 1250; t %= 1250; kt = t / 25; nt = t % 25;
        if (kt < 25) { src = W2; kb = kt * 8; } else { src = U2; kb = (kt - 25) * 8; }
    }
    int n  = nt * 8 + (lane >> 2);
    int kr = lane & 3;
    g_bf[(size_t)tile * 64 + lane * 2]     = tf32f(src[(kb + kr)     * 800 + gate * H_ + n]);
    g_bf[(size_t)tile * 64 + lane * 2 + 1] = tf32f(src[(kb + kr + 4) * 800 + gate * H_ + n]);
}

// ---------------- one gate's GEMM: C[2][7][4] = bias (+x*W0 for L0) + h @ Wgate ----------------
// A fragments of h live in smem: h[mt(4)][kt(25)][lane(32)][4] (uint4 per (mt,kt,lane)).
template<int L>
__device__ __forceinline__ void gate_gemm(
    float C[2][7][4], int gate,
    const float* hprev, const float* hcur,
    const float* __restrict__ bias, const float* __restrict__ W0, const float* xbuf,
    int wb, int ntbase, int cnt, int lane)
{
    constexpr int KT = (L == 0) ? 25 : 50;
    const size_t LOFF = (L == 0) ? 0 : (L == 1) ? (size_t)2500 * 64 : (size_t)7500 * 64;

    float xl0 = 0.f, xh0 = 0.f, xl1 = 0.f, xh1 = 0.f;
    if (L == 0) {
        int r = lane >> 2;
        xl0 = xbuf[wb * 32 + r];      xh0 = xbuf[wb * 32 + r + 8];
        xl1 = xbuf[wb * 32 + 16 + r]; xh1 = xbuf[wb * 32 + 24 + r];
    }
#pragma unroll
    for (int ni = 0; ni < 7; ++ni) {
        if (ni < cnt) {
            int j0 = (ntbase + ni) * 8 + 2 * (lane & 3);
            float b0 = __ldg(bias + gate * H_ + j0), b1 = __ldg(bias + gate * H_ + j0 + 1);
            if (L == 0) {
                float w0 = __ldg(W0 + gate * H_ + j0), w1 = __ldg(W0 + gate * H_ + j0 + 1);
                C[0][ni][0] = fmaf(xl0, w0, b0); C[0][ni][1] = fmaf(xl0, w1, b1);
                C[0][ni][2] = fmaf(xh0, w0, b0); C[0][ni][3] = fmaf(xh0, w1, b1);
                C[1][ni][0] = fmaf(xl1, w0, b0); C[1][ni][1] = fmaf(xl1, w1, b1);
                C[1][ni][2] = fmaf(xh1, w0, b0); C[1][ni][3] = fmaf(xh1, w1, b1);
            } else {
                C[0][ni][0] = b0; C[0][ni][1] = b1; C[0][ni][2] = b0; C[0][ni][3] = b1;
                C[1][ni][0] = b0; C[1][ni][1] = b1; C[1][ni][2] = b0; C[1][ni][3] = b1;
            }
        }
    }
    const float* bf = g_bf + LOFF + ((size_t)(gate * KT) * 25 + ntbase) * 64 + lane * 2;
    const int mt0 = wb * 2;

    // pass 1: K[0:200) against (L0 ? hcur : hprev)
    {
        const float* hA = (L == 0) ? hcur : hprev;
#pragma unroll 5
        for (int kt = 0; kt < 25; ++kt) {
            uint4 a0 = *(const uint4*)(hA + (((mt0    ) * 25 + kt) * 32 + lane) * 4);
            uint4 a1 = *(const uint4*)(hA + (((mt0 + 1) * 25 + kt) * 32 + lane) * 4);
            const float* bk = bf + (size_t)kt * 25 * 64;
#pragma unroll
            for (int ni = 0; ni < 7; ++ni) {
                if (ni < cnt) {
                    float2 bv = *(const float2*)(bk + ni * 64);
                    mma_tf32(C[0][ni], a0, bv);
                    mma_tf32(C[1][ni], a1, bv);
                }
            }
        }
    }
    // pass 2 (L>0): K[200:400) against hcur (recurrent U part)
    if (L > 0) {
#pragma unroll 5
        for (int kt = 0; kt < 25; ++kt) {
            uint4 a0 = *(const uint4*)(hcur + (((mt0    ) * 25 + kt) * 32 + lane) * 4);
            uint4 a1 = *(const uint4*)(hcur + (((mt0 + 1) * 25 + kt) * 32 + lane) * 4);
            const float* bk = bf + (size_t)(25 + kt) * 25 * 64;
#pragma unroll
            for (int ni = 0; ni < 7; ++ni) {
                if (ni < cnt) {
                    float2 bv = *(const float2*)(bk + ni * 64);
                    mma_tf32(C[0][ni], a0, bv);
                    mma_tf32(C[1][ni], a1, bv);
                }
            }
        }
    }
}

template<int L>
__device__ __forceinline__ void do_layer(
    const float* hprev, float* hcur, const float* xbuf,
    const float* __restrict__ bias, const float* __restrict__ W0,
    float* __restrict__ cb, int t, int wb, int ntbase, int cnt, int lane)
{
    float si[2][7][4], cn[2][7][4], C[2][7][4];
    // i gate
    gate_gemm<L>(C, 0, hprev, hcur, bias, W0, xbuf, wb, ntbase, cnt, lane);
#pragma unroll
    for (int mi = 0; mi < 2; ++mi)
#pragma unroll
    for (int ni = 0; ni < 7; ++ni) if (ni < cnt)
#pragma unroll
        for (int q = 0; q < 4; ++q) si[mi][ni][q] = sigm_(C[mi][ni][q]);
    // f gate -> cn = sigmoid(f) * c_old
    gate_gemm<L>(C, 1, hprev, hcur, bias, W0, xbuf, wb, ntbase, cnt, lane);
#pragma unroll
    for (int mi = 0; mi < 2; ++mi)
#pragma unroll
    for (int ni = 0; ni < 7; ++ni) if (ni < cnt) {
        float4 c4 = make_float4(0.f, 0.f, 0.f, 0.f);
        if (t > 0) c4 = *(const float4*)(cb + ((mi * 7 + ni) * 32 + lane) * 4);
        cn[mi][ni][0] = sigm_(C[mi][ni][0]) * c4.x;
        cn[mi][ni][1] = sigm_(C[mi][ni][1]) * c4.y;
        cn[mi][ni][2] = sigm_(C[mi][ni][2]) * c4.z;
        cn[mi][ni][3] = sigm_(C[mi][ni][3]) * c4.w;
    }
    // g gate -> cn += si * tanh(g); persist c
    gate_gemm<L>(C, 2, hprev, hcur, bias, W0, xbuf, wb, ntbase, cnt, lane);
#pragma unroll
    for (int mi = 0; mi < 2; ++mi)
#pragma unroll
    for (int ni = 0; ni < 7; ++ni) if (ni < cnt) {
#pragma unroll
        for (int q = 0; q < 4; ++q) cn[mi][ni][q] = fmaf(si[mi][ni][q], tanh_(C[mi][ni][q]), cn[mi][ni][q]);
        *(float4*)(cb + ((mi * 7 + ni) * 32 + lane) * 4) =
            make_float4(cn[mi][ni][0], cn[mi][ni][1], cn[mi][ni][2], cn[mi][ni][3]);
    }
    // o gate -> h = sigmoid(o) * tanh(cn)
    gate_gemm<L>(C, 3, hprev, hcur, bias, W0, xbuf, wb, ntbase, cnt, lane);
#pragma unroll
    for (int mi = 0; mi < 2; ++mi)
#pragma unroll
    for (int ni = 0; ni < 7; ++ni) if (ni < cnt)
#pragma unroll
        for (int q = 0; q < 4; ++q) C[mi][ni][q] = sigm_(C[mi][ni][q]) * tanh_(cn[mi][ni][q]);

    __syncthreads();   // all warps done reading old hcur fragments
    // write new h directly into A-fragment layout, tf32-rounded.
    // C elem (m,j): c0:(r, j0) c1:(r, j0+1) c2:(r+8, j0) c3:(r+8, j0+1), r=lane>>2, j0=nt*8+2*(lane&3)
    // A slot for (m,k): lane=(m%8)*4+(k&3), reg=(k&4?2:0)+(m>=8?1:0)
#pragma unroll
    for (int mi = 0; mi < 2; ++mi)
#pragma unroll
    for (int ni = 0; ni < 7; ++ni) if (ni < cnt) {
        int nt = ntbase + ni;
        int j0 = nt * 8 + 2 * (lane & 3);
        int r0 = (j0 & 4) ? 2 : 0;
        int l0 = ((lane >> 2) << 2) + (j0 & 3);
        float* base = hcur + (((wb * 2 + mi) * 25 + nt) * 32) * 4;
        *(float2*)(base + l0 * 4 + r0)       = make_float2(tf32f(C[mi][ni][0]), tf32f(C[mi][ni][2]));
        *(float2*)(base + (l0 + 1) * 4 + r0) = make_float2(tf32f(C[mi][ni][1]), tf32f(C[mi][ni][3]));
    }
    __syncthreads();   // new h visible to all warps
}

__global__ void __launch_bounds__(NTHREADS, 1) lstm_mma_kernel(
    const float* __restrict__ x,  const float* __restrict__ W0,
    const float* __restrict__ b0v, const float* __restrict__ b1v, const float* __restrict__ b2v,
    const float* __restrict__ Wfc, const float* __restrict__ bfc,
    float* __restrict__ out)
{
    extern __shared__ float sm[];
    float* hs0  = sm;            // [4 mt][25 kt][32][4] fragment layout, 12800 fl
    float* hs1  = sm + 12800;
    float* hs2  = sm + 25600;
    float* xbuf = sm + 38400;    // [64]

    const int tid = threadIdx.x, lane = tid & 31, wid = tid >> 5;
    const int wb = wid >> 2, wc = wid & 3;
    const int ntbase = (wc == 0) ? 0 : 1 + wc * 6;   // 0,7,13,19
    const int cnt    = (wc == 0) ? 7 : 6;
    const int bbase  = blockIdx.x * TILE_B;

    for (int i = tid; i < 3 * 12800; i += NTHREADS) sm[i] = 0.f;
    __syncthreads();

    float* cb0 = g_cbuf + (((size_t)blockIdx.x * 3 + 0) * 8 + wid) * 1792;
    float* cb1 = g_cbuf + (((size_t)blockIdx.x * 3 + 1) * 8 + wid) * 1792;
    float* cb2 = g_cbuf + (((size_t)blockIdx.x * 3 + 2) * 8 + wid) * 1792;

    for (int t = 0; t < T_; ++t) {
        if (tid < TILE_B) xbuf[tid] = x[(size_t)(bbase + tid) * T_ + t];
        __syncthreads();
        do_layer<0>(nullptr, hs0, xbuf, b0v, W0, cb0, t, wb, ntbase, cnt, lane);
        do_layer<1>(hs0,     hs1, xbuf, b1v, W0, cb1, t, wb, ntbase, cnt, lane);
        do_layer<2>(hs1,     hs2, xbuf, b2v, W0, cb2, t, wb, ntbase, cnt, lane);
    }

    // ---- reconstruct plain h2 [k][64] into hs0 (hs0 no longer needed) ----
    for (int idx = tid; idx < 4 * 25 * 32; idx += NTHREADS) {
        int tile = idx >> 5, ln = idx & 31;
        int mt = tile / 25, kt = tile % 25;
        float4 v = *(const float4*)(hs2 + (tile * 32 + ln) * 4);
        int m = mt * 16 + (ln >> 2), k = kt * 8 + (ln & 3);
        hs0[k * 64 + m]           = v.x;   // reg0: (m,   k)
        hs0[k * 64 + m + 8]       = v.y;   // reg1: (m+8, k)
        hs0[(k + 4) * 64 + m]     = v.z;   // reg2: (m,   k+4)
        hs0[(k + 4) * 64 + m + 8] = v.w;   // reg3: (m+8, k+4)
    }
    __syncthreads();

    // ---- dense head: y[b][m] = tanh(h2[b] @ Wfc[:,m] + bfc[m]) ----
    const int b = tid >> 2, mseg = tid & 3;
    for (int m0 = mseg * 100; m0 < mseg * 100 + 100; m0 += 4) {
        float4 acc = *(const float4*)(bfc + m0);
#pragma unroll 4
        for (int k = 0; k < H_; ++k) {
            float h = hs0[k * 64 + b];
            float4 w = *(const float4*)(Wfc + k * OUTC + m0);
            acc.x = fmaf(h, w.x, acc.x); acc.y = fmaf(h, w.y, acc.y);
            acc.z = fmaf(h, w.z, acc.z); acc.w = fmaf(h, w.w, acc.w);
        }
        *(float4*)(out + (size_t)(bbase + b) * OUTC + m0) =
            make_float4(tanh_(acc.x), tanh_(acc.y), tanh_(acc.z), tanh_(acc.w));
    }
}

extern "C" void kernel_launch(void* const* d_in, const int* in_sizes, int n_in,
                              void* d_out, int out_size) {
    (void)in_sizes; (void)n_in; (void)out_size;
    const float* x   = (const float*)d_in[0];
    const float* W0  = (const float*)d_in[1];
    const float* U0  = (const float*)d_in[2];
    const float* b0v = (const float*)d_in[3];
    const float* W1  = (const float*)d_in[4];
    const float* U1  = (const float*)d_in[5];
    const float* b1v = (const float*)d_in[6];
    const float* W2  = (const float*)d_in[7];
    const float* U2  = (const float*)d_in[8];
    const float* b2v = (const float*)d_in[9];
    const float* Wfc = (const float*)d_in[10];
    const float* bfc = (const float*)d_in[11];
    float* out = (float*)d_out;

    prep_kernel<<<(12500 * 32 + 255) / 256, 256>>>(U0, W1, U1, W2, U2);

    const int smem_bytes = (3 * 12800 + TILE_B) * (int)sizeof(float);   // 153,856 B
    cudaFuncSetAttribute(lstm_mma_kernel, cudaFuncAttributeMaxDynamicSharedMemorySize, smem_bytes);
    lstm_mma_kernel<<<NCTA, NTHREADS, smem_bytes>>>(
        x, W0, b0v, b1v, b2v, Wfc, bfc, out);
}